// round 15
// baseline (speedup 1.0000x reference)
#include <cuda_runtime.h>
#include <cuda_fp16.h>
#include <mma.h>
#include <cstdint>

using namespace nvcuda;

// Problem dims
#define BATCH 256
#define J_DIM 1024            // neurons (reduction of GEMM1)
#define K_DIM 1024            // n_feat  (M of GEMM1)
#define L_DIM 256             // in_dim
#define M_DIM 128             // out_dim (N of GEMM2)
#define LM    (L_DIM * M_DIM) // 32768   (N of GEMM1)
#define R_DIM (K_DIM * L_DIM) // 262144  (reduction of GEMM2)

// GEMM2 tiling: CTA 256x128 (whole batch), E read ONCE, fp32 X converted in-smem
#define BM2 256
#define BK2 32
#define LDXF 36                         // floats per Xf32 row (144 B)
#define LDXH 40                         // halves per Xf16 row (80 B)
#define LDE2 136                        // halves per E row (272 B)
#define XF32_BYTES (BM2 * LDXF * 4)     // 36864
#define E2_BYTES (BK2 * LDE2 * 2)       // 8704
#define STG2 (XF32_BYTES + E2_BYTES)    // 45568
#define NST2 3
#define XH_BYTES (BM2 * LDXH * 2)       // 20480
#define SMEM2 (NST2 * STG2 + XH_BYTES)  // 157184 (1 CTA/SM)
#define NSPLIT 256
#define SPLIT_LEN (R_DIM / NSPLIT)      // 1024
#define NCH2 (SPLIT_LEN / BK2)          // 32

// GEMM1 tiling: CTA 128x128x64, 4 warps of 64x64, 128 threads, 2 CTAs/SM
#define BM1 128
#define BN1 128
#define BK1 64
#define T1_THREADS 128
#define LDA1 72                        // halves (144 B rows)
#define LDB1 136                       // halves (272 B rows)
#define NST1 3
#define A1_BYTES (BM1 * LDA1 * 2)      // 18432
#define B1_BYTES (BK1 * LDB1 * 2)      // 17408
#define STG1 (A1_BYTES + B1_BYTES)     // 35840
#define SMEM1 (NST1 * STG1)            // 107520 (x2 CTAs = 215KB <= 228KB)
#define NCH1 (J_DIM / BK1)             // 16

// Scratch (static device globals — no allocation APIs allowed)
__device__ __half g_GT[(size_t)K_DIM * J_DIM];   //  2 MB : G^T fp16, (k, j)
__device__ __half g_D16[(size_t)J_DIM * LM];     // 64 MB : (v-w) fp16, (j, lm)
__device__ __half g_E[(size_t)K_DIM * LM];       // 64 MB : E fp16, (r, m)

// ---------------------------------------------------------------------------
// Helpers
// ---------------------------------------------------------------------------
__device__ __forceinline__ uint32_t smem_u32(const void* p) {
    uint32_t a;
    asm("{ .reg .u64 t; cvta.to.shared.u64 t, %1; cvt.u32.u64 %0, t; }" : "=r"(a) : "l"(p));
    return a;
}
#define CP_ASYNC16(dst, src) \
    asm volatile("cp.async.cg.shared.global [%0], [%1], 16;" :: "r"(dst), "l"(src))
#define CP_COMMIT() asm volatile("cp.async.commit_group;" ::: "memory")
#define CP_WAIT(n)  asm volatile("cp.async.wait_group %0;" :: "n"(n) : "memory")

// ---------------------------------------------------------------------------
// Convert kernels
// ---------------------------------------------------------------------------

// G (j,k) fp32 -> g_GT (k,j) fp16
__global__ void conv_GT_kernel(const float* __restrict__ G) {
    __shared__ float t[32][33];
    int jx = blockIdx.y * 32 + threadIdx.y;
    int kx = blockIdx.x * 32 + threadIdx.x;
    t[threadIdx.y][threadIdx.x] = G[jx * K_DIM + kx];
    __syncthreads();
    int ko = blockIdx.x * 32 + threadIdx.y;
    int jo = blockIdx.y * 32 + threadIdx.x;
    g_GT[(size_t)ko * J_DIM + jo] = __float2half(t[threadIdx.x][threadIdx.y]);
}

// g_D16 = fp16(v - w), elementwise, 4 elems/thread (streaming, coalesced)
__global__ void conv_D_kernel(const float* __restrict__ v, const float* __restrict__ w) {
    size_t i = (size_t)blockIdx.x * blockDim.x + threadIdx.x;  // float4 units
    float4 a = reinterpret_cast<const float4*>(v)[i];
    float4 b = reinterpret_cast<const float4*>(w)[i];
    __half2 lo = __floats2half2_rn(a.x - b.x, a.y - b.y);
    __half2 hi = __floats2half2_rn(a.z - b.z, a.w - b.w);
    __half2* dst = reinterpret_cast<__half2*>(&g_D16[i * 4]);
    dst[0] = lo;
    dst[1] = hi;
}

__global__ void zero_kernel(float* __restrict__ o) {
    int i = blockIdx.x * 256 + threadIdx.x;
    o[i] = 0.0f;
}

// ---------------------------------------------------------------------------
// GEMM1: E[k, n] = sum_j GT[k, j] * D16[j, n]
// CTA 128x128, BK=64, 3-stage cp.async, one barrier per chunk.
// 128 threads: 4 warps of 64x64. 2 CTAs/SM. grid (8, 256).
// ---------------------------------------------------------------------------
__global__ __launch_bounds__(T1_THREADS, 2) void gemm1_kernel5() {
    extern __shared__ char sm[];

    const int tid  = threadIdx.x;
    const int warp = tid >> 5;
    const int lane = tid & 31;
    const int wm   = warp >> 1;   // 0..1  (64-row slab)
    const int wn   = warp & 1;    // 0..1  (64-col slab)
    const int mBase = blockIdx.x * BM1;
    const int nBase = blockIdx.y * BN1;

    const uint32_t smem_base = smem_u32(sm);

    wmma::fragment<wmma::accumulator, 16, 16, 16, float> acc[4][4];
#pragma unroll
    for (int i = 0; i < 4; i++)
#pragma unroll
        for (int j = 0; j < 4; j++)
            wmma::fill_fragment(acc[i][j], 0.0f);

    auto fill = [&](int s, int chunk) {
        uint32_t a_base = smem_base + s * STG1;
        uint32_t b_base = a_base + A1_BYTES;
#pragma unroll
        for (int u = tid; u < 1024; u += T1_THREADS) {
            int row = u >> 3, c = u & 7;
            uint32_t dst = a_base + row * (LDA1 * 2) + c * 16;
            const void* src = &g_GT[(size_t)(mBase + row) * J_DIM + chunk * BK1 + c * 8];
            CP_ASYNC16(dst, src);
        }
#pragma unroll
        for (int u = tid; u < 1024; u += T1_THREADS) {
            int row = u >> 4, c = u & 15;
            uint32_t dst = b_base + row * (LDB1 * 2) + c * 16;
            const void* src = &g_D16[(size_t)(chunk * BK1 + row) * LM + nBase + c * 8];
            CP_ASYNC16(dst, src);
        }
        CP_COMMIT();
    };

#pragma unroll
    for (int s = 0; s < NST1; s++) fill(s, s);

#pragma unroll 1
    for (int i = 0; i < NCH1; i++) {
        const int s = i % NST1;
        if (i < NCH1 - 1) CP_WAIT(1);
        else              CP_WAIT(0);
        __syncthreads();   // chunk i resident; all warps done with chunk i-1

        if (i >= 1 && i + 2 < NCH1)
            fill((i + 2) % NST1, i + 2);   // overwrite slot (i-1)%3, now free

        const __half* As = reinterpret_cast<const __half*>(sm + s * STG1);
        const __half* Bs = reinterpret_cast<const __half*>(sm + s * STG1 + A1_BYTES);

#pragma unroll
        for (int kk = 0; kk < BK1 / 16; kk++) {
            wmma::fragment<wmma::matrix_a, 16, 16, 16, __half, wmma::row_major> af[4];
            wmma::fragment<wmma::matrix_b, 16, 16, 16, __half, wmma::row_major> bf[4];
#pragma unroll
            for (int ii = 0; ii < 4; ii++)
                wmma::load_matrix_sync(af[ii],
                    &As[(wm * 64 + ii * 16) * LDA1 + kk * 16], LDA1);
#pragma unroll
            for (int j = 0; j < 4; j++)
                wmma::load_matrix_sync(bf[j],
                    &Bs[(kk * 16) * LDB1 + wn * 64 + j * 16], LDB1);
#pragma unroll
            for (int ii = 0; ii < 4; ii++)
#pragma unroll
                for (int j = 0; j < 4; j++)
                    wmma::mma_sync(acc[ii][j], af[ii], bf[j], acc[ii][j]);
        }
    }

    __syncthreads();   // smem free for epilogue staging

    float* stg = reinterpret_cast<float*>(sm) + warp * 256;
    const int r  = lane >> 1;
    const int c8 = (lane & 1) * 8;
#pragma unroll
    for (int i = 0; i < 4; i++)
#pragma unroll
        for (int j = 0; j < 4; j++) {
            wmma::store_matrix_sync(stg, acc[i][j], 16, wmma::mem_row_major);
            __syncwarp();
            const float* sp = &stg[r * 16 + c8];
            __half2 h[4];
#pragma unroll
            for (int p = 0; p < 4; p++)
                h[p] = __floats2half2_rn(sp[2 * p], sp[2 * p + 1]);
            size_t off = (size_t)(mBase + wm * 64 + i * 16 + r) * LM
                       + nBase + wn * 64 + j * 16 + c8;
            *reinterpret_cast<uint4*>(&g_E[off]) = *reinterpret_cast<uint4*>(h);
            __syncwarp();
        }
}

// ---------------------------------------------------------------------------
// GEMM2: out[i, m] += sum_r fp16(x[i, r]) * E[r, m]
// CTA covers the FULL batch (BM2=256) so each E chunk is read exactly once.
// 3-stage cp.async pipeline; X staged fp32, converted to fp16 in smem.
// grid (NSPLIT=256), 256 threads (8 warps, 4x2 of 64x64). 1 CTA/SM.
// ---------------------------------------------------------------------------
__global__ __launch_bounds__(256) void gemm2_kernel4(const float* __restrict__ X,
                                                     float* __restrict__ out) {
    extern __shared__ char sm[];

    const int tid  = threadIdx.x;
    const int warp = tid >> 5;
    const int lane = tid & 31;
    const int wm   = warp >> 1;   // 0..3  (64-row slab)
    const int wn   = warp & 1;    // 0..1  (64-col slab)
    const int kStart = blockIdx.x * SPLIT_LEN;

    const uint32_t smem_base = smem_u32(sm);
    __half* xh = reinterpret_cast<__half*>(sm + NST2 * STG2);

    wmma::fragment<wmma::accumulator, 16, 16, 16, float> acc[4][4];
#pragma unroll
    for (int i = 0; i < 4; i++)
#pragma unroll
        for (int j = 0; j < 4; j++)
            wmma::fill_fragment(acc[i][j], 0.0f);

    auto fill = [&](int s, int chunk) {
        uint32_t x_base = smem_base + s * STG2;
        uint32_t e_base = x_base + XF32_BYTES;
        int k0 = kStart + chunk * BK2;
#pragma unroll
        for (int u = tid; u < 2048; u += 256) {       // X: 256 rows x 8 x 16B (fp32)
            int row = u >> 3, c = u & 7;
            uint32_t dst = x_base + row * (LDXF * 4) + c * 16;
            const void* src = &X[(size_t)row * R_DIM + k0 + c * 4];
            CP_ASYNC16(dst, src);
        }
#pragma unroll
        for (int u = tid; u < 512; u += 256) {        // E: 32 rows x 16 x 16B (fp16)
            int row = u >> 4, c = u & 15;
            uint32_t dst = e_base + row * (LDE2 * 2) + c * 16;
            const void* src = &g_E[(size_t)(k0 + row) * M_DIM + c * 8];
            CP_ASYNC16(dst, src);
        }
        CP_COMMIT();
    };

#pragma unroll
    for (int s = 0; s < NST2; s++) fill(s, s);

#pragma unroll 1
    for (int i = 0; i < NCH2; i++) {
        const int s = i % NST2;
        if (i < NCH2 - 1) CP_WAIT(1);
        else              CP_WAIT(0);
        __syncthreads();   // chunk i resident; prior iter fully consumed

        if (i >= 1 && i + 2 < NCH2)
            fill((i + 2) % NST2, i + 2);

        // Convert X fp32 (slot s) -> fp16 (shared single buffer)
        {
            const float* xf = reinterpret_cast<const float*>(sm + s * STG2);
#pragma unroll
            for (int u = tid; u < 1024; u += 256) {   // 256 rows x 4 x (8 halves)
                int row = u >> 2, q = u & 3;
                float4 a = *reinterpret_cast<const float4*>(&xf[row * LDXF + q * 8]);
                float4 b = *reinterpret_cast<const float4*>(&xf[row * LDXF + q * 8 + 4]);
                __half2 h[4];
                h[0] = __floats2half2_rn(a.x, a.y);
                h[1] = __floats2half2_rn(a.z, a.w);
                h[2] = __floats2half2_rn(b.x, b.y);
                h[3] = __floats2half2_rn(b.z, b.w);
                *reinterpret_cast<uint4*>(&xh[row * LDXH + q * 8]) =
                    *reinterpret_cast<uint4*>(h);
            }
        }
        __syncthreads();   // converted tile visible to all warps

        const __half* Bs = reinterpret_cast<const __half*>(sm + s * STG2 + XF32_BYTES);
#pragma unroll
        for (int kk = 0; kk < BK2; kk += 16) {
            wmma::fragment<wmma::matrix_a, 16, 16, 16, __half, wmma::row_major> af[4];
            wmma::fragment<wmma::matrix_b, 16, 16, 16, __half, wmma::row_major> bf[4];
#pragma unroll
            for (int ii = 0; ii < 4; ii++)
                wmma::load_matrix_sync(af[ii], &xh[(wm * 64 + ii * 16) * LDXH + kk], LDXH);
#pragma unroll
            for (int j = 0; j < 4; j++)
                wmma::load_matrix_sync(bf[j], &Bs[kk * LDE2 + wn * 64 + j * 16], LDE2);
#pragma unroll
            for (int ii = 0; ii < 4; ii++)
#pragma unroll
                for (int j = 0; j < 4; j++)
                    wmma::mma_sync(acc[ii][j], af[ii], bf[j], acc[ii][j]);
        }
    }

    __syncthreads();   // smem free for epilogue staging

    float* stg = reinterpret_cast<float*>(sm) + warp * 256;
    const int r  = lane >> 1;
    const int c8 = (lane & 1) * 8;
#pragma unroll
    for (int i = 0; i < 4; i++)
#pragma unroll
        for (int j = 0; j < 4; j++) {
            wmma::store_matrix_sync(stg, acc[i][j], 16, wmma::mem_row_major);
            __syncwarp();
            const float* sp = &stg[r * 16 + c8];
            int gm = wm * 64 + i * 16 + r;
            int gn = wn * 64 + j * 16 + c8;
#pragma unroll
            for (int t = 0; t < 8; t++)
                atomicAdd(&out[gm * M_DIM + gn + t], sp[t]);
            __syncwarp();
        }
}

// ---------------------------------------------------------------------------
// Launch
// ---------------------------------------------------------------------------
extern "C" void kernel_launch(void* const* d_in, const int* in_sizes, int n_in,
                              void* d_out, int out_size) {
    const float* x = (const float*)d_in[0];   // (256, 1024, 256)
    const float* G = (const float*)d_in[1];   // (1024, 1024)
    const float* v = (const float*)d_in[2];   // (1024, 256, 128)
    const float* w = (const float*)d_in[3];   // (1024, 256, 128)
    float* out = (float*)d_out;               // (256, 128)

    // Idempotent, non-stream API calls: capture-legal, no static guards.
    cudaFuncSetAttribute(gemm1_kernel5,
                         cudaFuncAttributeMaxDynamicSharedMemorySize, SMEM1);
    cudaFuncSetAttribute(gemm2_kernel4,
                         cudaFuncAttributeMaxDynamicSharedMemorySize, SMEM2);

    conv_GT_kernel<<<dim3(32, 32), dim3(32, 32)>>>(G);
    conv_D_kernel<<<(J_DIM * (size_t)LM) / (4 * 256), 256>>>(v, w);
    zero_kernel<<<(BATCH * M_DIM) / 256, 256>>>(out);
    gemm1_kernel5<<<dim3(K_DIM / BM1, LM / BN1), T1_THREADS, SMEM1>>>();
    gemm2_kernel4<<<NSPLIT, 256, SMEM2>>>(x, out);
}

// round 17
// speedup vs baseline: 1.2675x; 1.2675x over previous
#include <cuda_runtime.h>
#include <cuda_fp16.h>
#include <mma.h>
#include <cstdint>

using namespace nvcuda;

// Problem dims
#define BATCH 256
#define J_DIM 1024            // neurons (reduction of GEMM1)
#define K_DIM 1024            // n_feat  (M of GEMM1)
#define L_DIM 256             // in_dim
#define M_DIM 128             // out_dim (N of GEMM2)
#define LM    (L_DIM * M_DIM) // 32768   (N of GEMM1)
#define R_DIM (K_DIM * L_DIM) // 262144  (reduction of GEMM2)

// GEMM2 tiling (pipelined; X staged fp32 -> fp16 in smem)
#define BM 128
#define BK2 32
#define LDA_S 40                        // halves per Xf16 row (80 B)
#define LDE2 136                        // halves per E row (272 B)
#define LDXF 36                         // floats per Xf32 row (144 B)
#define XF32_BYTES (BM * LDXF * 4)      // 18432
#define E2_BYTES (BK2 * LDE2 * 2)       // 8704
#define STG2 (XF32_BYTES + E2_BYTES)    // 27136
#define NST2 3
#define XF16_BYTES (BM * LDA_S * 2)     // 10240
#define SMEM2 (NST2 * STG2 + XF16_BYTES) // 91648 (x2 CTAs = 183KB <= 228KB)
#define NSPLIT 128
#define SPLIT_LEN (R_DIM / NSPLIT)      // 2048
#define NCH2 (SPLIT_LEN / BK2)          // 64

// GEMM1 tiling: CTA 128x128x64, 4 warps of 64x64, 128 threads, 2 CTAs/SM
#define BM1 128
#define BN1 128
#define BK1 64
#define T1_THREADS 128
#define LDA1 72                        // halves (144 B rows)
#define LDB1 136                       // halves (272 B rows)
#define NST1 3
#define A1_BYTES (BM1 * LDA1 * 2)      // 18432
#define B1_BYTES (BK1 * LDB1 * 2)      // 17408
#define STG1 (A1_BYTES + B1_BYTES)     // 35840
#define SMEM1 (NST1 * STG1)            // 107520 (x2 CTAs = 215KB <= 228KB)
#define NCH1 (J_DIM / BK1)             // 16

// Scratch (static device globals — no allocation APIs allowed)
__device__ __half g_GT[(size_t)K_DIM * J_DIM];   //  2 MB : G^T fp16, (k, j)
__device__ __half g_D16[(size_t)J_DIM * LM];     // 64 MB : (v-w) fp16, (j, lm)
__device__ __half g_E[(size_t)K_DIM * LM];       // 64 MB : E fp16, (r, m)

// ---------------------------------------------------------------------------
// Helpers
// ---------------------------------------------------------------------------
__device__ __forceinline__ uint32_t smem_u32(const void* p) {
    uint32_t a;
    asm("{ .reg .u64 t; cvta.to.shared.u64 t, %1; cvt.u32.u64 %0, t; }" : "=r"(a) : "l"(p));
    return a;
}
#define CP_ASYNC16(dst, src) \
    asm volatile("cp.async.cg.shared.global [%0], [%1], 16;" :: "r"(dst), "l"(src))
#define CP_COMMIT() asm volatile("cp.async.commit_group;" ::: "memory")
#define CP_WAIT(n)  asm volatile("cp.async.wait_group %0;" :: "n"(n) : "memory")

// ---------------------------------------------------------------------------
// Convert kernels
// ---------------------------------------------------------------------------

// G (j,k) fp32 -> g_GT (k,j) fp16
__global__ void conv_GT_kernel(const float* __restrict__ G) {
    __shared__ float t[32][33];
    int jx = blockIdx.y * 32 + threadIdx.y;
    int kx = blockIdx.x * 32 + threadIdx.x;
    t[threadIdx.y][threadIdx.x] = G[jx * K_DIM + kx];
    __syncthreads();
    int ko = blockIdx.x * 32 + threadIdx.y;
    int jo = blockIdx.y * 32 + threadIdx.x;
    g_GT[(size_t)ko * J_DIM + jo] = __float2half(t[threadIdx.x][threadIdx.y]);
}

// g_D16 = fp16(v - w), elementwise, 4 elems/thread (streaming, coalesced)
__global__ void conv_D_kernel(const float* __restrict__ v, const float* __restrict__ w) {
    size_t i = (size_t)blockIdx.x * blockDim.x + threadIdx.x;  // float4 units
    float4 a = reinterpret_cast<const float4*>(v)[i];
    float4 b = reinterpret_cast<const float4*>(w)[i];
    __half2 lo = __floats2half2_rn(a.x - b.x, a.y - b.y);
    __half2 hi = __floats2half2_rn(a.z - b.z, a.w - b.w);
    __half2* dst = reinterpret_cast<__half2*>(&g_D16[i * 4]);
    dst[0] = lo;
    dst[1] = hi;
}

__global__ void zero_kernel(float* __restrict__ o) {
    int i = blockIdx.x * 256 + threadIdx.x;
    o[i] = 0.0f;
}

// ---------------------------------------------------------------------------
// GEMM1: E[k, n] = sum_j GT[k, j] * D16[j, n]
// CTA 128x128, BK=64, 3-stage cp.async, one barrier per chunk.
// 128 threads: 4 warps of 64x64. 2 CTAs/SM. grid (8, 256).
// ---------------------------------------------------------------------------
__global__ __launch_bounds__(T1_THREADS, 2) void gemm1_kernel5() {
    extern __shared__ char sm[];

    const int tid  = threadIdx.x;
    const int warp = tid >> 5;
    const int lane = tid & 31;
    const int wm   = warp >> 1;   // 0..1  (64-row slab)
    const int wn   = warp & 1;    // 0..1  (64-col slab)
    const int mBase = blockIdx.x * BM1;
    const int nBase = blockIdx.y * BN1;

    const uint32_t smem_base = smem_u32(sm);

    wmma::fragment<wmma::accumulator, 16, 16, 16, float> acc[4][4];
#pragma unroll
    for (int i = 0; i < 4; i++)
#pragma unroll
        for (int j = 0; j < 4; j++)
            wmma::fill_fragment(acc[i][j], 0.0f);

    auto fill = [&](int s, int chunk) {
        uint32_t a_base = smem_base + s * STG1;
        uint32_t b_base = a_base + A1_BYTES;
#pragma unroll
        for (int u = tid; u < 1024; u += T1_THREADS) {
            int row = u >> 3, c = u & 7;
            uint32_t dst = a_base + row * (LDA1 * 2) + c * 16;
            const void* src = &g_GT[(size_t)(mBase + row) * J_DIM + chunk * BK1 + c * 8];
            CP_ASYNC16(dst, src);
        }
#pragma unroll
        for (int u = tid; u < 1024; u += T1_THREADS) {
            int row = u >> 4, c = u & 15;
            uint32_t dst = b_base + row * (LDB1 * 2) + c * 16;
            const void* src = &g_D16[(size_t)(chunk * BK1 + row) * LM + nBase + c * 8];
            CP_ASYNC16(dst, src);
        }
        CP_COMMIT();
    };

#pragma unroll
    for (int s = 0; s < NST1; s++) fill(s, s);

#pragma unroll 1
    for (int i = 0; i < NCH1; i++) {
        const int s = i % NST1;
        if (i < NCH1 - 1) CP_WAIT(1);
        else              CP_WAIT(0);
        __syncthreads();   // chunk i resident; all warps done with chunk i-1

        if (i >= 1 && i + 2 < NCH1)
            fill((i + 2) % NST1, i + 2);   // overwrite slot (i-1)%3, now free

        const __half* As = reinterpret_cast<const __half*>(sm + s * STG1);
        const __half* Bs = reinterpret_cast<const __half*>(sm + s * STG1 + A1_BYTES);

#pragma unroll
        for (int kk = 0; kk < BK1 / 16; kk++) {
            wmma::fragment<wmma::matrix_a, 16, 16, 16, __half, wmma::row_major> af[4];
            wmma::fragment<wmma::matrix_b, 16, 16, 16, __half, wmma::row_major> bf[4];
#pragma unroll
            for (int ii = 0; ii < 4; ii++)
                wmma::load_matrix_sync(af[ii],
                    &As[(wm * 64 + ii * 16) * LDA1 + kk * 16], LDA1);
#pragma unroll
            for (int j = 0; j < 4; j++)
                wmma::load_matrix_sync(bf[j],
                    &Bs[(kk * 16) * LDB1 + wn * 64 + j * 16], LDB1);
#pragma unroll
            for (int ii = 0; ii < 4; ii++)
#pragma unroll
                for (int j = 0; j < 4; j++)
                    wmma::mma_sync(acc[ii][j], af[ii], bf[j], acc[ii][j]);
        }
    }

    __syncthreads();   // smem free for epilogue staging

    float* stg = reinterpret_cast<float*>(sm) + warp * 256;
    const int r  = lane >> 1;
    const int c8 = (lane & 1) * 8;
#pragma unroll
    for (int i = 0; i < 4; i++)
#pragma unroll
        for (int j = 0; j < 4; j++) {
            wmma::store_matrix_sync(stg, acc[i][j], 16, wmma::mem_row_major);
            __syncwarp();
            const float* sp = &stg[r * 16 + c8];
            __half2 h[4];
#pragma unroll
            for (int p = 0; p < 4; p++)
                h[p] = __floats2half2_rn(sp[2 * p], sp[2 * p + 1]);
            size_t off = (size_t)(mBase + wm * 64 + i * 16 + r) * LM
                       + nBase + wn * 64 + j * 16 + c8;
            *reinterpret_cast<uint4*>(&g_E[off]) = *reinterpret_cast<uint4*>(h);
            __syncwarp();
        }
}

// ---------------------------------------------------------------------------
// GEMM2: out[i, m] += sum_r fp16(x[i, r]) * E[r, m]
// 3-stage cp.async pipeline: X staged fp32, converted to fp16 in smem.
// grid (2, NSPLIT): mBase varies FASTEST so the two CTAs sharing a k-split
// are adjacent/co-resident -> second E read hits L2 (E never read twice
// from DRAM). 256 threads (8 warps, 4x2 of 32x64). 2 CTAs/SM.
// ---------------------------------------------------------------------------
__global__ __launch_bounds__(256, 2) void gemm2_kernel2(const float* __restrict__ X,
                                                        float* __restrict__ out) {
    extern __shared__ char sm[];

    const int tid  = threadIdx.x;
    const int warp = tid >> 5;
    const int lane = tid & 31;
    const int wm   = warp >> 1;   // 0..3  (32-row slab)
    const int wn   = warp & 1;    // 0..1  (64-col slab)
    const int mBase  = blockIdx.x * BM;          // fastest-varying
    const int kStart = blockIdx.y * SPLIT_LEN;

    const uint32_t smem_base = smem_u32(sm);
    __half* xh = reinterpret_cast<__half*>(sm + NST2 * STG2);

    wmma::fragment<wmma::accumulator, 16, 16, 16, float> acc[2][4];
#pragma unroll
    for (int i = 0; i < 2; i++)
#pragma unroll
        for (int j = 0; j < 4; j++)
            wmma::fill_fragment(acc[i][j], 0.0f);

    auto fill = [&](int s, int chunk) {
        uint32_t x_base = smem_base + s * STG2;
        uint32_t e_base = x_base + XF32_BYTES;
        int k0 = kStart + chunk * BK2;
#pragma unroll
        for (int u = tid; u < 1024; u += 256) {       // X: 128 rows x 8 x 16B (fp32)
            int row = u >> 3, c = u & 7;
            uint32_t dst = x_base + row * (LDXF * 4) + c * 16;
            const void* src = &X[(size_t)(mBase + row) * R_DIM + k0 + c * 4];
            CP_ASYNC16(dst, src);
        }
#pragma unroll
        for (int u = tid; u < 512; u += 256) {        // E: 32 rows x 16 x 16B (fp16)
            int row = u >> 4, c = u & 15;
            uint32_t dst = e_base + row * (LDE2 * 2) + c * 16;
            const void* src = &g_E[(size_t)(k0 + row) * M_DIM + c * 8];
            CP_ASYNC16(dst, src);
        }
        CP_COMMIT();
    };

#pragma unroll
    for (int s = 0; s < NST2; s++) fill(s, s);

#pragma unroll 1
    for (int i = 0; i < NCH2; i++) {
        const int s = i % NST2;
        if (i < NCH2 - 1) CP_WAIT(1);
        else              CP_WAIT(0);
        __syncthreads();   // chunk i resident; prior iter fully consumed

        if (i >= 1 && i + 2 < NCH2)
            fill((i + 2) % NST2, i + 2);

        // Convert X fp32 (slot s) -> fp16 (shared single buffer)
        {
            const float* xf = reinterpret_cast<const float*>(sm + s * STG2);
#pragma unroll
            for (int u = tid; u < 512; u += 256) {    // 128 rows x 4 x (8 halves)
                int row = u >> 2, q = u & 3;
                float4 a = *reinterpret_cast<const float4*>(&xf[row * LDXF + q * 8]);
                float4 b = *reinterpret_cast<const float4*>(&xf[row * LDXF + q * 8 + 4]);
                __half2 h[4];
                h[0] = __floats2half2_rn(a.x, a.y);
                h[1] = __floats2half2_rn(a.z, a.w);
                h[2] = __floats2half2_rn(b.x, b.y);
                h[3] = __floats2half2_rn(b.z, b.w);
                *reinterpret_cast<uint4*>(&xh[row * LDA_S + q * 8]) =
                    *reinterpret_cast<uint4*>(h);
            }
        }
        __syncthreads();   // converted tile visible to all warps

        const __half* Bs = reinterpret_cast<const __half*>(sm + s * STG2 + XF32_BYTES);
#pragma unroll
        for (int kk = 0; kk < BK2; kk += 16) {
            wmma::fragment<wmma::matrix_a, 16, 16, 16, __half, wmma::row_major> af[2];
            wmma::fragment<wmma::matrix_b, 16, 16, 16, __half, wmma::row_major> bf[4];
#pragma unroll
            for (int ii = 0; ii < 2; ii++)
                wmma::load_matrix_sync(af[ii], &xh[(wm * 32 + ii * 16) * LDA_S + kk], LDA_S);
#pragma unroll
            for (int j = 0; j < 4; j++)
                wmma::load_matrix_sync(bf[j], &Bs[kk * LDE2 + wn * 64 + j * 16], LDE2);
#pragma unroll
            for (int ii = 0; ii < 2; ii++)
#pragma unroll
                for (int j = 0; j < 4; j++)
                    wmma::mma_sync(acc[ii][j], af[ii], bf[j], acc[ii][j]);
        }
    }

    __syncthreads();   // smem free for epilogue staging

    float* stg = reinterpret_cast<float*>(sm) + warp * 256;
    const int r  = lane >> 1;
    const int c8 = (lane & 1) * 8;
#pragma unroll
    for (int i = 0; i < 2; i++)
#pragma unroll
        for (int j = 0; j < 4; j++) {
            wmma::store_matrix_sync(stg, acc[i][j], 16, wmma::mem_row_major);
            __syncwarp();
            const float* sp = &stg[r * 16 + c8];
            int gm = mBase + wm * 32 + i * 16 + r;
            int gn = wn * 64 + j * 16 + c8;
#pragma unroll
            for (int t = 0; t < 8; t++)
                atomicAdd(&out[gm * M_DIM + gn + t], sp[t]);
            __syncwarp();
        }
}

// ---------------------------------------------------------------------------
// Launch
// ---------------------------------------------------------------------------
extern "C" void kernel_launch(void* const* d_in, const int* in_sizes, int n_in,
                              void* d_out, int out_size) {
    const float* x = (const float*)d_in[0];   // (256, 1024, 256)
    const float* G = (const float*)d_in[1];   // (1024, 1024)
    const float* v = (const float*)d_in[2];   // (1024, 256, 128)
    const float* w = (const float*)d_in[3];   // (1024, 256, 128)
    float* out = (float*)d_out;               // (256, 128)

    // Idempotent, non-stream API calls: capture-legal, no static guards.
    cudaFuncSetAttribute(gemm1_kernel5,
                         cudaFuncAttributeMaxDynamicSharedMemorySize, SMEM1);
    cudaFuncSetAttribute(gemm2_kernel2,
                         cudaFuncAttributeMaxDynamicSharedMemorySize, SMEM2);

    conv_GT_kernel<<<dim3(32, 32), dim3(32, 32)>>>(G);
    conv_D_kernel<<<(J_DIM * (size_t)LM) / (4 * 256), 256>>>(v, w);
    zero_kernel<<<(BATCH * M_DIM) / 256, 256>>>(out);
    gemm1_kernel5<<<dim3(K_DIM / BM1, LM / BN1), T1_THREADS, SMEM1>>>();
    gemm2_kernel2<<<dim3(2, NSPLIT), 256, SMEM2>>>(x, out);
}